// round 9
// baseline (speedup 1.0000x reference)
#include <cuda_runtime.h>
#include <math_constants.h>

// x/bias/a/b : [4,128,128,256] f32 NHWC; 2x2/2 argmax-pool of x, gather from
// all 4 tensors at the argmax, plus global truncation-interval reduction.
// d_out: out_x | out_bias | out_a | out_b | l | u (flattened).
namespace {
constexpr int Hh = 128, Ww = 128, Cc = 256, Hp = 64, Wp = 64;
constexpr int NOUT = 4 * Hp * Wp * Cc;    // 4,194,304 per output tensor
constexpr int N2   = NOUT / 2;            // 2,097,152 vec2 outputs
constexpr int C2   = Cc / 2;              // 128 (float2 units along C)
constexpr int WC2  = Ww * C2;             // 16384
constexpr int SCAL = 4 * NOUT;            // scalar slots: l, u
constexpr int TPB  = 512;                 // threads per block
constexpr int NBLK = N2 / TPB;            // 4096 blocks
}

// Global reduction lattice (statically seeded; finalizer resets for replay).
// All accesses are L2 atomics (RMW) -> coherent without fences.
__device__ unsigned int g_lbits = 0xFF800000u;   // running max (lower bound cand.)
__device__ unsigned int g_ubits = 0x7F800000u;   // running min (upper bound cand.)
__device__ unsigned int g_count = 0;

__device__ __forceinline__ float getc(const float2& v, int k) { return k == 0 ? v.x : v.y; }
__device__ __forceinline__ void  setc(float2& v, int k, float f) { if (k == 0) v.x = f; else v.y = f; }
__device__ __forceinline__ float sel4(float v0, float v1, float v2, float v3, int k) {
    return k == 0 ? v0 : (k == 1 ? v1 : (k == 2 ? v2 : v3));
}

// Exact float max/min atomics via sign-aware integer ordering (relaxed).
__device__ __forceinline__ void atomicMaxF(unsigned int* addr, float v) {
    if (v >= 0.0f) atomicMax((int*)addr, __float_as_int(v));
    else           atomicMin(addr, __float_as_uint(v));
}
__device__ __forceinline__ void atomicMinF(unsigned int* addr, float v) {
    if (v >= 0.0f) atomicMin((int*)addr, __float_as_int(v));
    else           atomicMax(addr, __float_as_uint(v));
}

__global__ void __launch_bounds__(TPB, 4)
pool_kernel(const float2* __restrict__ x,
            const float2* __restrict__ bias,
            const float2* __restrict__ a,
            const float2* __restrict__ b,
            const float* __restrict__ lin,
            const float* __restrict__ uin,
            float* __restrict__ out) {
    float2* __restrict__ out2 = reinterpret_cast<float2*>(out);

    const int i = blockIdx.x * TPB + threadIdx.x;   // exactly N2 threads
    // i = (((bb*Hp + hp)*Wp + wp)*C2 + c2)
    int c2 = i & (C2 - 1);
    int t  = i >> 7;            // C2 == 128
    int wp = t & (Wp - 1);
    t >>= 6;
    int hp = t & (Hp - 1);
    int bb = t >> 6;
    const int base = ((bb * Hh + 2 * hp) * Ww + 2 * wp) * C2 + c2;
    // Window order matches reference patches: (0,0),(0,1),(1,0),(1,1)
    const int o1 = C2, o2 = WC2, o3 = WC2 + C2;

    // ---- Phase 1: x -> argmax + out_x ----
    const float2 X0 = __ldcs(x + base), X1 = __ldcs(x + base + o1),
                 X2 = __ldcs(x + base + o2), X3 = __ldcs(x + base + o3);
    int idx[2];
    float2 ox;
    #pragma unroll
    for (int ln = 0; ln < 2; ln++) {
        float v0 = getc(X0, ln), v1 = getc(X1, ln), v2 = getc(X2, ln), v3 = getc(X3, ln);
        int k = 0; float best = v0;                       // first-max (strict >)
        if (v1 > best) { best = v1; k = 1; }
        if (v2 > best) { best = v2; k = 2; }
        if (v3 > best) { best = v3; k = 3; }
        idx[ln] = k;
        setc(ox, ln, best);
    }
    __stcs(out2 + i, ox);

    // ---- Phase 2: bias -> out_bias + partial noms (bis - bi_j) ----
    const float2 I0 = __ldcs(bias + base), I1 = __ldcs(bias + base + o1),
                 I2 = __ldcs(bias + base + o2), I3 = __ldcs(bias + base + o3);
    float nb[2][4];
    float2 obi;
    #pragma unroll
    for (int ln = 0; ln < 2; ln++) {
        float v0 = getc(I0, ln), v1 = getc(I1, ln), v2 = getc(I2, ln), v3 = getc(I3, ln);
        float s = sel4(v0, v1, v2, v3, idx[ln]);
        setc(obi, ln, s);
        nb[ln][0] = s - v0; nb[ln][1] = s - v1; nb[ln][2] = s - v2; nb[ln][3] = s - v3;
    }
    __stcs(out2 + N2 + i, obi);

    // ---- Phase 3: a -> out_a + full noms (nb + (as - a_j)) ----
    const float2 A0 = __ldcs(a + base), A1 = __ldcs(a + base + o1),
                 A2 = __ldcs(a + base + o2), A3 = __ldcs(a + base + o3);
    float2 oa;
    #pragma unroll
    for (int ln = 0; ln < 2; ln++) {
        float v0 = getc(A0, ln), v1 = getc(A1, ln), v2 = getc(A2, ln), v3 = getc(A3, ln);
        float s = sel4(v0, v1, v2, v3, idx[ln]);
        setc(oa, ln, s);
        nb[ln][0] += s - v0; nb[ln][1] += s - v1; nb[ln][2] += s - v2; nb[ln][3] += s - v3;
    }
    __stcs(out2 + 2 * N2 + i, oa);

    // ---- Phase 4: b -> out_b + interval candidates (branchless) ----
    float lloc = -CUDART_INF_F;
    float uloc =  CUDART_INF_F;
    const float2 B0 = __ldcs(b + base), B1 = __ldcs(b + base + o1),
                 B2 = __ldcs(b + base + o2), B3 = __ldcs(b + base + o3);
    float2 ob;
    #pragma unroll
    for (int ln = 0; ln < 2; ln++) {
        float v0 = getc(B0, ln), v1 = getc(B1, ln), v2 = getc(B2, ln), v3 = getc(B3, ln);
        float s = sel4(v0, v1, v2, v3, idx[ln]);
        setc(ob, ln, s);
        float d[4] = { v0 - s, v1 - s, v2 - s, v3 - s };
        #pragma unroll
        for (int j = 0; j < 4; j++) {
            // j==idx: 0/0 -> NaN, but both guards are false, so never used.
            float q = __fdividef(nb[ln][j], d[j]);
            uloc = (d[j] > 0.0f) ? fminf(uloc, q) : uloc;
            lloc = (d[j] < 0.0f) ? fmaxf(lloc, q) : lloc;
        }
    }
    __stcs(out2 + 3 * N2 + i, ob);

    // ---- Block reduction: warp shuffle -> shared -> 3 relaxed atomics ----
    #pragma unroll
    for (int off = 16; off; off >>= 1) {
        lloc = fmaxf(lloc, __shfl_xor_sync(0xffffffffu, lloc, off));
        uloc = fminf(uloc, __shfl_xor_sync(0xffffffffu, uloc, off));
    }
    __shared__ float sl[16], su[16];
    const int warp = threadIdx.x >> 5;
    const int lane = threadIdx.x & 31;
    if (lane == 0) { sl[warp] = lloc; su[warp] = uloc; }
    __syncthreads();
    if (threadIdx.x == 0) {
        // Fold block partials AND the input l/u clamp (L2-broadcast loads).
        float lb = fmaxf(sl[0], __ldg(lin));
        float ub = fminf(su[0], __ldg(uin));
        #pragma unroll
        for (int w = 1; w < TPB / 32; w++) {
            lb = fmaxf(lb, sl[w]);
            ub = fminf(ub, su[w]);
        }
        // Relaxed L2 RMWs — no fences, no acquire, no L1 flush.
        atomicMaxF(&g_lbits, lb);
        atomicMinF(&g_ubits, ub);
        if (atomicAdd(&g_count, 1u) == (unsigned)(NBLK - 1)) {
            // Last arriver: read lattice via relaxed RMWs (L2-coherent, never
            // stale-L1), write the two scalars, reset lattice for replay.
            out[SCAL]     = __uint_as_float(atomicAdd(&g_lbits, 0u));
            out[SCAL + 1] = __uint_as_float(atomicAdd(&g_ubits, 0u));
            atomicExch(&g_lbits, 0xFF800000u);
            atomicExch(&g_ubits, 0x7F800000u);
            atomicExch(&g_count, 0u);   // kernel boundary orders for next replay
        }
    }
}

extern "C" void kernel_launch(void* const* d_in, const int* in_sizes, int n_in,
                              void* d_out, int out_size) {
    const float2* x  = (const float2*)d_in[0];
    const float2* bi = (const float2*)d_in[1];
    const float2* a  = (const float2*)d_in[2];
    const float2* b  = (const float2*)d_in[3];
    const float*  l  = (const float*)d_in[4];
    const float*  u  = (const float*)d_in[5];
    float* out = (float*)d_out;

    pool_kernel<<<NBLK, TPB>>>(x, bi, a, b, l, u, out);   // single kernel
}

// round 10
// speedup vs baseline: 1.1236x; 1.1236x over previous
#include <cuda_runtime.h>
#include <math_constants.h>

// x/bias/a/b : [4,128,128,256] f32 NHWC; 2x2/2 argmax-pool of x, gather from
// all 4 tensors at the argmax, plus global truncation-interval reduction.
// d_out: out_x | out_bias | out_a | out_b | l | u (flattened).
namespace {
constexpr int Hh = 128, Ww = 128, Cc = 256, Hp = 64, Wp = 64;
constexpr int NOUT = 4 * Hp * Wp * Cc;    // 4,194,304 per output tensor
constexpr int N2   = NOUT / 2;            // 2,097,152 vec2 outputs
constexpr int C2   = Cc / 2;              // 128 (float2 units along C)
constexpr int WC2  = Ww * C2;             // 16384
constexpr int SCAL = 4 * NOUT;            // scalar slots: l, u
constexpr int TPB  = 256;                 // proven-best CTA shape (8/SM, 32 regs)
constexpr int NBLK = N2 / TPB;            // 8192 blocks
}

// Global reduction lattice (statically seeded; finalizer resets for replay).
// All accesses are relaxed L2 atomics (RMW) -> coherent without fences.
__device__ unsigned int g_lbits = 0xFF800000u;   // running max (lower bound cand.)
__device__ unsigned int g_ubits = 0x7F800000u;   // running min (upper bound cand.)
__device__ unsigned int g_count = 0;

__device__ __forceinline__ float getc(const float2& v, int k) { return k == 0 ? v.x : v.y; }
__device__ __forceinline__ void  setc(float2& v, int k, float f) { if (k == 0) v.x = f; else v.y = f; }
__device__ __forceinline__ float sel4(float v0, float v1, float v2, float v3, int k) {
    return k == 0 ? v0 : (k == 1 ? v1 : (k == 2 ? v2 : v3));
}

// Exact float max/min atomics via sign-aware integer ordering (relaxed).
// Note: atomicMaxF(addr, -inf) and atomicMinF(addr, +inf) are exact no-ops
// in this encoding, so callers may invoke them unconditionally.
__device__ __forceinline__ void atomicMaxF(unsigned int* addr, float v) {
    if (v >= 0.0f) atomicMax((int*)addr, __float_as_int(v));
    else           atomicMin(addr, __float_as_uint(v));
}
__device__ __forceinline__ void atomicMinF(unsigned int* addr, float v) {
    if (v >= 0.0f) atomicMin((int*)addr, __float_as_int(v));
    else           atomicMax(addr, __float_as_uint(v));
}

__global__ void __launch_bounds__(TPB, 8)
pool_kernel(const float2* __restrict__ x,
            const float2* __restrict__ bias,
            const float2* __restrict__ a,
            const float2* __restrict__ b,
            const float* __restrict__ lin,
            const float* __restrict__ uin,
            float* __restrict__ out) {
    float2* __restrict__ out2 = reinterpret_cast<float2*>(out);

    const int i = blockIdx.x * TPB + threadIdx.x;   // exactly N2 threads
    // i = (((bb*Hp + hp)*Wp + wp)*C2 + c2)
    int c2 = i & (C2 - 1);
    int t  = i >> 7;            // C2 == 128
    int wp = t & (Wp - 1);
    t >>= 6;
    int hp = t & (Hp - 1);
    int bb = t >> 6;
    const int base = ((bb * Hh + 2 * hp) * Ww + 2 * wp) * C2 + c2;
    // Window order matches reference patches: (0,0),(0,1),(1,0),(1,1)
    const int o1 = C2, o2 = WC2, o3 = WC2 + C2;

    // ---- Phase 1: x -> argmax + out_x ----
    const float2 X0 = __ldcs(x + base), X1 = __ldcs(x + base + o1),
                 X2 = __ldcs(x + base + o2), X3 = __ldcs(x + base + o3);
    int idx[2];
    float2 ox;
    #pragma unroll
    for (int ln = 0; ln < 2; ln++) {
        float v0 = getc(X0, ln), v1 = getc(X1, ln), v2 = getc(X2, ln), v3 = getc(X3, ln);
        int k = 0; float best = v0;                       // first-max (strict >)
        if (v1 > best) { best = v1; k = 1; }
        if (v2 > best) { best = v2; k = 2; }
        if (v3 > best) { best = v3; k = 3; }
        idx[ln] = k;
        setc(ox, ln, best);
    }
    __stcs(out2 + i, ox);

    // ---- Phase 2: bias -> out_bias + partial noms (bis - bi_j) ----
    const float2 I0 = __ldcs(bias + base), I1 = __ldcs(bias + base + o1),
                 I2 = __ldcs(bias + base + o2), I3 = __ldcs(bias + base + o3);
    float nb[2][4];
    float2 obi;
    #pragma unroll
    for (int ln = 0; ln < 2; ln++) {
        float v0 = getc(I0, ln), v1 = getc(I1, ln), v2 = getc(I2, ln), v3 = getc(I3, ln);
        float s = sel4(v0, v1, v2, v3, idx[ln]);
        setc(obi, ln, s);
        nb[ln][0] = s - v0; nb[ln][1] = s - v1; nb[ln][2] = s - v2; nb[ln][3] = s - v3;
    }
    __stcs(out2 + N2 + i, obi);

    // ---- Phase 3: a -> out_a + full noms (nb + (as - a_j)) ----
    const float2 A0 = __ldcs(a + base), A1 = __ldcs(a + base + o1),
                 A2 = __ldcs(a + base + o2), A3 = __ldcs(a + base + o3);
    float2 oa;
    #pragma unroll
    for (int ln = 0; ln < 2; ln++) {
        float v0 = getc(A0, ln), v1 = getc(A1, ln), v2 = getc(A2, ln), v3 = getc(A3, ln);
        float s = sel4(v0, v1, v2, v3, idx[ln]);
        setc(oa, ln, s);
        nb[ln][0] += s - v0; nb[ln][1] += s - v1; nb[ln][2] += s - v2; nb[ln][3] += s - v3;
    }
    __stcs(out2 + 2 * N2 + i, oa);

    // ---- Phase 4: b -> out_b + interval candidates (branchless) ----
    float lloc = -CUDART_INF_F;
    float uloc =  CUDART_INF_F;
    const float2 B0 = __ldcs(b + base), B1 = __ldcs(b + base + o1),
                 B2 = __ldcs(b + base + o2), B3 = __ldcs(b + base + o3);
    float2 ob;
    #pragma unroll
    for (int ln = 0; ln < 2; ln++) {
        float v0 = getc(B0, ln), v1 = getc(B1, ln), v2 = getc(B2, ln), v3 = getc(B3, ln);
        float s = sel4(v0, v1, v2, v3, idx[ln]);
        setc(ob, ln, s);
        float d[4] = { v0 - s, v1 - s, v2 - s, v3 - s };
        #pragma unroll
        for (int j = 0; j < 4; j++) {
            // j==idx: 0/0 -> NaN, but both guards are false, so never used.
            float q = __fdividef(nb[ln][j], d[j]);
            uloc = (d[j] > 0.0f) ? fminf(uloc, q) : uloc;
            lloc = (d[j] < 0.0f) ? fmaxf(lloc, q) : lloc;
        }
    }
    __stcs(out2 + 3 * N2 + i, ob);

    // ---- Block reduction: warp shuffle -> shared -> 3 relaxed atomics ----
    #pragma unroll
    for (int off = 16; off; off >>= 1) {
        lloc = fmaxf(lloc, __shfl_xor_sync(0xffffffffu, lloc, off));
        uloc = fminf(uloc, __shfl_xor_sync(0xffffffffu, uloc, off));
    }
    __shared__ float sl[8], su[8];
    const int warp = threadIdx.x >> 5;
    const int lane = threadIdx.x & 31;
    if (lane == 0) { sl[warp] = lloc; su[warp] = uloc; }
    __syncthreads();
    if (threadIdx.x == 0) {
        // Fold block partials AND the input l/u clamp (L2-broadcast loads).
        float lb = fmaxf(sl[0], __ldg(lin));
        float ub = fminf(su[0], __ldg(uin));
        #pragma unroll
        for (int w = 1; w < TPB / 32; w++) {
            lb = fmaxf(lb, sl[w]);
            ub = fminf(ub, su[w]);
        }
        // Unconditional relaxed L2 RMWs (no-op-safe at the +-inf identities).
        atomicMaxF(&g_lbits, lb);
        atomicMinF(&g_ubits, ub);
        if (atomicAdd(&g_count, 1u) == (unsigned)(NBLK - 1)) {
            // Last arriver: read lattice via relaxed RMWs (L2-coherent, never
            // stale-L1), write the two scalars, reset lattice for replay.
            out[SCAL]     = __uint_as_float(atomicAdd(&g_lbits, 0u));
            out[SCAL + 1] = __uint_as_float(atomicAdd(&g_ubits, 0u));
            atomicExch(&g_lbits, 0xFF800000u);
            atomicExch(&g_ubits, 0x7F800000u);
            atomicExch(&g_count, 0u);   // kernel boundary orders for next replay
        }
    }
}

extern "C" void kernel_launch(void* const* d_in, const int* in_sizes, int n_in,
                              void* d_out, int out_size) {
    const float2* x  = (const float2*)d_in[0];
    const float2* bi = (const float2*)d_in[1];
    const float2* a  = (const float2*)d_in[2];
    const float2* b  = (const float2*)d_in[3];
    const float*  l  = (const float*)d_in[4];
    const float*  u  = (const float*)d_in[5];
    float* out = (float*)d_out;

    pool_kernel<<<NBLK, TPB>>>(x, bi, a, b, l, u, out);   // single kernel
}

// round 11
// speedup vs baseline: 1.1462x; 1.0201x over previous
#include <cuda_runtime.h>
#include <math_constants.h>

// x/bias/a/b : [4,128,128,256] f32 NHWC; 2x2/2 argmax-pool of x, gather from
// all 4 tensors at the argmax, plus global truncation-interval reduction.
// d_out: out_x | out_bias | out_a | out_b | l | u (flattened).
namespace {
constexpr int Hh = 128, Ww = 128, Cc = 256, Hp = 64, Wp = 64;
constexpr int NOUT = 4 * Hp * Wp * Cc;    // 4,194,304 per output tensor
constexpr int N2   = NOUT / 2;            // 2,097,152 vec2 outputs
constexpr int C2   = Cc / 2;              // 128 (float2 units along C)
constexpr int WC2  = Ww * C2;             // 16384
constexpr int SCAL = 4 * NOUT;            // scalar slots: l, u
constexpr int TPB  = 256;                 // proven-best CTA shape (8/SM, 32 regs)
constexpr int NBLK = N2 / TPB;            // 8192 blocks
}

// Global reduction lattice (statically seeded; finalizer resets for replay).
// All accesses are relaxed L2 atomics (RMW) -> coherent without fences.
__device__ unsigned int g_lbits = 0xFF800000u;   // running max (lower bound cand.)
__device__ unsigned int g_ubits = 0x7F800000u;   // running min (upper bound cand.)
__device__ unsigned int g_count = 0;

__device__ __forceinline__ float getc(const float2& v, int k) { return k == 0 ? v.x : v.y; }
__device__ __forceinline__ void  setc(float2& v, int k, float f) { if (k == 0) v.x = f; else v.y = f; }
__device__ __forceinline__ float sel4(float v0, float v1, float v2, float v3, int k) {
    return k == 0 ? v0 : (k == 1 ? v1 : (k == 2 ? v2 : v3));
}

// Exact float max/min atomics via sign-aware integer ordering (relaxed).
// atomicMaxF(addr, -inf) / atomicMinF(addr, +inf) are exact no-ops in this
// encoding, so callers may invoke them unconditionally.
__device__ __forceinline__ void atomicMaxF(unsigned int* addr, float v) {
    if (v >= 0.0f) atomicMax((int*)addr, __float_as_int(v));
    else           atomicMin(addr, __float_as_uint(v));
}
__device__ __forceinline__ void atomicMinF(unsigned int* addr, float v) {
    if (v >= 0.0f) atomicMin((int*)addr, __float_as_int(v));
    else           atomicMax(addr, __float_as_uint(v));
}

__global__ void __launch_bounds__(TPB, 8)
pool_kernel(const float2* __restrict__ x,
            const float2* __restrict__ bias,
            const float2* __restrict__ a,
            const float2* __restrict__ b,
            const float* __restrict__ lin,
            const float* __restrict__ uin,
            float* __restrict__ out) {
    float2* __restrict__ out2 = reinterpret_cast<float2*>(out);

    const int i = blockIdx.x * TPB + threadIdx.x;   // exactly N2 threads
    // i = (((bb*Hp + hp)*Wp + wp)*C2 + c2)
    int c2 = i & (C2 - 1);
    int t  = i >> 7;            // C2 == 128
    int wp = t & (Wp - 1);
    t >>= 6;
    int hp = t & (Hp - 1);
    int bb = t >> 6;
    const int base = ((bb * Hh + 2 * hp) * Ww + 2 * wp) * C2 + c2;
    // Window order matches reference patches: (0,0),(0,1),(1,0),(1,1)
    const int o1 = C2, o2 = WC2, o3 = WC2 + C2;

    // ---- Phase 1: x -> argmax + out_x ----
    const float2 X0 = __ldcs(x + base), X1 = __ldcs(x + base + o1),
                 X2 = __ldcs(x + base + o2), X3 = __ldcs(x + base + o3);
    int idx[2];
    float2 ox;
    #pragma unroll
    for (int ln = 0; ln < 2; ln++) {
        float v0 = getc(X0, ln), v1 = getc(X1, ln), v2 = getc(X2, ln), v3 = getc(X3, ln);
        int k = 0; float best = v0;                       // first-max (strict >)
        if (v1 > best) { best = v1; k = 1; }
        if (v2 > best) { best = v2; k = 2; }
        if (v3 > best) { best = v3; k = 3; }
        idx[ln] = k;
        setc(ox, ln, best);
    }
    __stcs(out2 + i, ox);

    // ---- Phase 2: bias -> out_bias + partial noms (bis - bi_j) ----
    const float2 I0 = __ldcs(bias + base), I1 = __ldcs(bias + base + o1),
                 I2 = __ldcs(bias + base + o2), I3 = __ldcs(bias + base + o3);
    float nb[2][4];
    float2 obi;
    #pragma unroll
    for (int ln = 0; ln < 2; ln++) {
        float v0 = getc(I0, ln), v1 = getc(I1, ln), v2 = getc(I2, ln), v3 = getc(I3, ln);
        float s = sel4(v0, v1, v2, v3, idx[ln]);
        setc(obi, ln, s);
        nb[ln][0] = s - v0; nb[ln][1] = s - v1; nb[ln][2] = s - v2; nb[ln][3] = s - v3;
    }
    __stcs(out2 + N2 + i, obi);

    // ---- Phase 3: a -> out_a + full noms (nb + (as - a_j)) ----
    const float2 A0 = __ldcs(a + base), A1 = __ldcs(a + base + o1),
                 A2 = __ldcs(a + base + o2), A3 = __ldcs(a + base + o3);
    float2 oa;
    #pragma unroll
    for (int ln = 0; ln < 2; ln++) {
        float v0 = getc(A0, ln), v1 = getc(A1, ln), v2 = getc(A2, ln), v3 = getc(A3, ln);
        float s = sel4(v0, v1, v2, v3, idx[ln]);
        setc(oa, ln, s);
        nb[ln][0] += s - v0; nb[ln][1] += s - v1; nb[ln][2] += s - v2; nb[ln][3] += s - v3;
    }
    __stcs(out2 + 2 * N2 + i, oa);

    // ---- Phase 4: b -> out_b + interval candidates (branchless) ----
    float lloc = -CUDART_INF_F;
    float uloc =  CUDART_INF_F;
    const float2 B0 = __ldcs(b + base), B1 = __ldcs(b + base + o1),
                 B2 = __ldcs(b + base + o2), B3 = __ldcs(b + base + o3);
    float2 ob;
    #pragma unroll
    for (int ln = 0; ln < 2; ln++) {
        float v0 = getc(B0, ln), v1 = getc(B1, ln), v2 = getc(B2, ln), v3 = getc(B3, ln);
        float s = sel4(v0, v1, v2, v3, idx[ln]);
        setc(ob, ln, s);
        float d[4] = { v0 - s, v1 - s, v2 - s, v3 - s };
        #pragma unroll
        for (int j = 0; j < 4; j++) {
            // j==idx: 0/0 -> NaN, but both guards are false, so never used.
            float q = __fdividef(nb[ln][j], d[j]);
            uloc = (d[j] > 0.0f) ? fminf(uloc, q) : uloc;
            lloc = (d[j] < 0.0f) ? fmaxf(lloc, q) : lloc;
        }
    }
    __stcs(out2 + 3 * N2 + i, ob);

    // ---- Block reduction: warp shuffle -> shared -> 3 relaxed atomics ----
    #pragma unroll
    for (int off = 16; off; off >>= 1) {
        lloc = fmaxf(lloc, __shfl_xor_sync(0xffffffffu, lloc, off));
        uloc = fminf(uloc, __shfl_xor_sync(0xffffffffu, uloc, off));
    }
    __shared__ float sl[8], su[8];
    const int warp = threadIdx.x >> 5;
    const int lane = threadIdx.x & 31;
    if (lane == 0) { sl[warp] = lloc; su[warp] = uloc; }
    __syncthreads();
    if (threadIdx.x == 0) {
        float lb = sl[0], ub = su[0];
        #pragma unroll
        for (int w = 1; w < TPB / 32; w++) {
            lb = fmaxf(lb, sl[w]);
            ub = fminf(ub, su[w]);
        }
        // Unconditional relaxed L2 RMWs (no-op-safe at the +-inf identities).
        atomicMaxF(&g_lbits, lb);
        atomicMinF(&g_ubits, ub);
        if (atomicAdd(&g_count, 1u) == (unsigned)(NBLK - 1)) {
            // Last arriver: read lattice via relaxed RMWs (L2-coherent, never
            // stale-L1), clamp with input l/u, write the two output scalars,
            // reset the lattice for the next graph replay.
            float lf = __uint_as_float(atomicAdd(&g_lbits, 0u));
            float uf = __uint_as_float(atomicAdd(&g_ubits, 0u));
            out[SCAL]     = fmaxf(lin[0], lf);
            out[SCAL + 1] = fminf(uin[0], uf);
            atomicExch(&g_lbits, 0xFF800000u);
            atomicExch(&g_ubits, 0x7F800000u);
            atomicExch(&g_count, 0u);   // kernel boundary orders for next replay
        }
    }
}

extern "C" void kernel_launch(void* const* d_in, const int* in_sizes, int n_in,
                              void* d_out, int out_size) {
    const float2* x  = (const float2*)d_in[0];
    const float2* bi = (const float2*)d_in[1];
    const float2* a  = (const float2*)d_in[2];
    const float2* b  = (const float2*)d_in[3];
    const float*  l  = (const float*)d_in[4];
    const float*  u  = (const float*)d_in[5];
    float* out = (float*)d_out;

    pool_kernel<<<NBLK, TPB>>>(x, bi, a, b, l, u, out);   // single kernel
}

// round 12
// speedup vs baseline: 1.1524x; 1.0054x over previous
#include <cuda_runtime.h>
#include <math_constants.h>

// x/bias/a/b : [4,128,128,256] f32 NHWC; 2x2/2 argmax-pool of x, gather from
// all 4 tensors at the argmax, plus global truncation-interval reduction.
// d_out: out_x | out_bias | out_a | out_b | l | u (flattened).
namespace {
constexpr int Hh = 128, Ww = 128, Cc = 256, Hp = 64, Wp = 64;
constexpr int NOUT = 4 * Hp * Wp * Cc;    // 4,194,304 per output tensor
constexpr int N2   = NOUT / 2;            // 2,097,152 vec2 outputs
constexpr int C2   = Cc / 2;              // 128 (float2 units along C)
constexpr int WC2  = Ww * C2;             // 16384
constexpr int SCAL = 4 * NOUT;            // scalar slots: l, u
constexpr int TPB  = 256;                 // proven-best CTA shape (8/SM, 32 regs)
constexpr int NBLK = N2 / TPB;            // 8192 blocks
}

// Global reduction lattice (statically seeded; finalizer resets for replay).
// All accesses are relaxed L2 atomics (RMW) -> coherent without fences.
__device__ unsigned int g_lbits = 0xFF800000u;   // running max (lower bound cand.)
__device__ unsigned int g_ubits = 0x7F800000u;   // running min (upper bound cand.)
__device__ unsigned int g_count = 0;

__device__ __forceinline__ float getc(const float2& v, int k) { return k == 0 ? v.x : v.y; }
__device__ __forceinline__ void  setc(float2& v, int k, float f) { if (k == 0) v.x = f; else v.y = f; }
__device__ __forceinline__ float sel4(float v0, float v1, float v2, float v3, int k) {
    return k == 0 ? v0 : (k == 1 ? v1 : (k == 2 ? v2 : v3));
}

// Exact float max/min atomics via sign-aware integer ordering (relaxed).
// atomicMaxF(addr, -inf) / atomicMinF(addr, +inf) are exact no-ops in this
// encoding, so callers may invoke them unconditionally.
__device__ __forceinline__ void atomicMaxF(unsigned int* addr, float v) {
    if (v >= 0.0f) atomicMax((int*)addr, __float_as_int(v));
    else           atomicMin(addr, __float_as_uint(v));
}
__device__ __forceinline__ void atomicMinF(unsigned int* addr, float v) {
    if (v >= 0.0f) atomicMin((int*)addr, __float_as_int(v));
    else           atomicMax(addr, __float_as_uint(v));
}

__global__ void __launch_bounds__(TPB, 8)
pool_kernel(const float2* __restrict__ x,
            const float2* __restrict__ bias,
            const float2* __restrict__ a,
            const float2* __restrict__ b,
            const float* __restrict__ lin,
            const float* __restrict__ uin,
            float* __restrict__ out) {
    float2* __restrict__ out2 = reinterpret_cast<float2*>(out);

    const int i = blockIdx.x * TPB + threadIdx.x;   // exactly N2 threads
    // i = (((bb*Hp + hp)*Wp + wp)*C2 + c2)
    int c2 = i & (C2 - 1);
    int t  = i >> 7;            // C2 == 128
    int wp = t & (Wp - 1);
    t >>= 6;
    int hp = t & (Hp - 1);
    int bb = t >> 6;
    const int base = ((bb * Hh + 2 * hp) * Ww + 2 * wp) * C2 + c2;
    // Window order matches reference patches: (0,0),(0,1),(1,0),(1,1)
    const int o1 = C2, o2 = WC2, o3 = WC2 + C2;

    // Inputs: streaming (evict-first) loads — each byte read exactly once,
    // and they must NOT displace the dirty write-back output lines in L2.
    // Outputs: DEFAULT write-back stores — 64 MB fits in the 126 MB L2, so
    // dirty lines drain lazily instead of contending with the read stream.

    // ---- Phase 1: x -> argmax + out_x ----
    const float2 X0 = __ldcs(x + base), X1 = __ldcs(x + base + o1),
                 X2 = __ldcs(x + base + o2), X3 = __ldcs(x + base + o3);
    int idx[2];
    float2 ox;
    #pragma unroll
    for (int ln = 0; ln < 2; ln++) {
        float v0 = getc(X0, ln), v1 = getc(X1, ln), v2 = getc(X2, ln), v3 = getc(X3, ln);
        int k = 0; float best = v0;                       // first-max (strict >)
        if (v1 > best) { best = v1; k = 1; }
        if (v2 > best) { best = v2; k = 2; }
        if (v3 > best) { best = v3; k = 3; }
        idx[ln] = k;
        setc(ox, ln, best);
    }
    out2[i] = ox;

    // ---- Phase 2: bias -> out_bias + partial noms (bis - bi_j) ----
    const float2 I0 = __ldcs(bias + base), I1 = __ldcs(bias + base + o1),
                 I2 = __ldcs(bias + base + o2), I3 = __ldcs(bias + base + o3);
    float nb[2][4];
    float2 obi;
    #pragma unroll
    for (int ln = 0; ln < 2; ln++) {
        float v0 = getc(I0, ln), v1 = getc(I1, ln), v2 = getc(I2, ln), v3 = getc(I3, ln);
        float s = sel4(v0, v1, v2, v3, idx[ln]);
        setc(obi, ln, s);
        nb[ln][0] = s - v0; nb[ln][1] = s - v1; nb[ln][2] = s - v2; nb[ln][3] = s - v3;
    }
    out2[N2 + i] = obi;

    // ---- Phase 3: a -> out_a + full noms (nb + (as - a_j)) ----
    const float2 A0 = __ldcs(a + base), A1 = __ldcs(a + base + o1),
                 A2 = __ldcs(a + base + o2), A3 = __ldcs(a + base + o3);
    float2 oa;
    #pragma unroll
    for (int ln = 0; ln < 2; ln++) {
        float v0 = getc(A0, ln), v1 = getc(A1, ln), v2 = getc(A2, ln), v3 = getc(A3, ln);
        float s = sel4(v0, v1, v2, v3, idx[ln]);
        setc(oa, ln, s);
        nb[ln][0] += s - v0; nb[ln][1] += s - v1; nb[ln][2] += s - v2; nb[ln][3] += s - v3;
    }
    out2[2 * N2 + i] = oa;

    // ---- Phase 4: b -> out_b + interval candidates (branchless) ----
    float lloc = -CUDART_INF_F;
    float uloc =  CUDART_INF_F;
    const float2 B0 = __ldcs(b + base), B1 = __ldcs(b + base + o1),
                 B2 = __ldcs(b + base + o2), B3 = __ldcs(b + base + o3);
    float2 ob;
    #pragma unroll
    for (int ln = 0; ln < 2; ln++) {
        float v0 = getc(B0, ln), v1 = getc(B1, ln), v2 = getc(B2, ln), v3 = getc(B3, ln);
        float s = sel4(v0, v1, v2, v3, idx[ln]);
        setc(ob, ln, s);
        float d[4] = { v0 - s, v1 - s, v2 - s, v3 - s };
        #pragma unroll
        for (int j = 0; j < 4; j++) {
            // j==idx: 0/0 -> NaN, but both guards are false, so never used.
            float q = __fdividef(nb[ln][j], d[j]);
            uloc = (d[j] > 0.0f) ? fminf(uloc, q) : uloc;
            lloc = (d[j] < 0.0f) ? fmaxf(lloc, q) : lloc;
        }
    }
    out2[3 * N2 + i] = ob;

    // ---- Block reduction: warp shuffle -> shared -> 3 relaxed atomics ----
    #pragma unroll
    for (int off = 16; off; off >>= 1) {
        lloc = fmaxf(lloc, __shfl_xor_sync(0xffffffffu, lloc, off));
        uloc = fminf(uloc, __shfl_xor_sync(0xffffffffu, uloc, off));
    }
    __shared__ float sl[8], su[8];
    const int warp = threadIdx.x >> 5;
    const int lane = threadIdx.x & 31;
    if (lane == 0) { sl[warp] = lloc; su[warp] = uloc; }
    __syncthreads();
    if (threadIdx.x == 0) {
        float lb = sl[0], ub = su[0];
        #pragma unroll
        for (int w = 1; w < TPB / 32; w++) {
            lb = fmaxf(lb, sl[w]);
            ub = fminf(ub, su[w]);
        }
        // Unconditional relaxed L2 RMWs (no-op-safe at the +-inf identities).
        atomicMaxF(&g_lbits, lb);
        atomicMinF(&g_ubits, ub);
        if (atomicAdd(&g_count, 1u) == (unsigned)(NBLK - 1)) {
            // Last arriver: read lattice via relaxed RMWs (L2-coherent, never
            // stale-L1), clamp with input l/u, write the two output scalars,
            // reset the lattice for the next graph replay.
            float lf = __uint_as_float(atomicAdd(&g_lbits, 0u));
            float uf = __uint_as_float(atomicAdd(&g_ubits, 0u));
            out[SCAL]     = fmaxf(lin[0], lf);
            out[SCAL + 1] = fminf(uin[0], uf);
            atomicExch(&g_lbits, 0xFF800000u);
            atomicExch(&g_ubits, 0x7F800000u);
            atomicExch(&g_count, 0u);   // kernel boundary orders for next replay
        }
    }
}

extern "C" void kernel_launch(void* const* d_in, const int* in_sizes, int n_in,
                              void* d_out, int out_size) {
    const float2* x  = (const float2*)d_in[0];
    const float2* bi = (const float2*)d_in[1];
    const float2* a  = (const float2*)d_in[2];
    const float2* b  = (const float2*)d_in[3];
    const float*  l  = (const float*)d_in[4];
    const float*  u  = (const float*)d_in[5];
    float* out = (float*)d_out;

    pool_kernel<<<NBLK, TPB>>>(x, bi, a, b, l, u, out);   // single kernel
}

// round 14
// speedup vs baseline: 1.1607x; 1.0072x over previous
#include <cuda_runtime.h>
#include <math_constants.h>

// x/bias/a/b : [4,128,128,256] f32 NHWC; 2x2/2 argmax-pool of x, gather from
// all 4 tensors at the argmax, plus global truncation-interval reduction.
// d_out: out_x | out_bias | out_a | out_b | l | u (flattened).
namespace {
constexpr int Hh = 128, Ww = 128, Cc = 256, Hp = 64, Wp = 64;
constexpr int NOUT = 4 * Hp * Wp * Cc;    // 4,194,304 per output tensor
constexpr int N2   = NOUT / 2;            // 2,097,152 vec2 outputs
constexpr int C2   = Cc / 2;              // 128 (float2 units along C)
constexpr int WC2  = Ww * C2;             // 16384
constexpr int SCAL = 4 * NOUT;            // scalar slots: l, u
constexpr int TPB  = 256;                 // proven-best CTA shape (8/SM, 32 regs)
constexpr int NBLK = N2 / TPB;            // 8192 blocks
}

// Global reduction lattice (statically seeded; finalizer resets for replay).
// All accesses are relaxed L2 atomics (RMW) -> coherent without fences.
__device__ unsigned int g_lbits = 0xFF800000u;   // running max (lower bound cand.)
__device__ unsigned int g_ubits = 0x7F800000u;   // running min (upper bound cand.)
__device__ unsigned int g_count = 0;

__device__ __forceinline__ float getc(const float2& v, int k) { return k == 0 ? v.x : v.y; }
__device__ __forceinline__ void  setc(float2& v, int k, float f) { if (k == 0) v.x = f; else v.y = f; }
__device__ __forceinline__ float sel4(float v0, float v1, float v2, float v3, int k) {
    return k == 0 ? v0 : (k == 1 ? v1 : (k == 2 ? v2 : v3));
}

// L2 evict_last access policy (descriptor form — the immediate .L2::evict_last
// store modifier requires 256-bit stores on sm_103a; cache_hint has no width
// restriction). Dirty output lines pinned at lowest eviction priority stay
// L2-resident across graph replays (64 MB outputs << 126 MB L2), so the next
// replay overwrites them in place and the DRAM writeback is elided.
__device__ __forceinline__ unsigned long long mk_evict_last_policy() {
    unsigned long long p;
    asm("createpolicy.fractional.L2::evict_last.b64 %0, 1.0;" : "=l"(p));
    return p;
}
__device__ __forceinline__ void st_hint(float2* p, float2 v, unsigned long long pol) {
    asm volatile("st.global.L2::cache_hint.v2.f32 [%0], {%1, %2}, %3;"
                 :: "l"(p), "f"(v.x), "f"(v.y), "l"(pol) : "memory");
}

// Exact float max/min atomics via sign-aware integer ordering (relaxed).
// atomicMaxF(addr, -inf) / atomicMinF(addr, +inf) are exact no-ops in this
// encoding, so callers may invoke them unconditionally.
__device__ __forceinline__ void atomicMaxF(unsigned int* addr, float v) {
    if (v >= 0.0f) atomicMax((int*)addr, __float_as_int(v));
    else           atomicMin(addr, __float_as_uint(v));
}
__device__ __forceinline__ void atomicMinF(unsigned int* addr, float v) {
    if (v >= 0.0f) atomicMin((int*)addr, __float_as_int(v));
    else           atomicMax(addr, __float_as_uint(v));
}

__global__ void __launch_bounds__(TPB, 8)
pool_kernel(const float2* __restrict__ x,
            const float2* __restrict__ bias,
            const float2* __restrict__ a,
            const float2* __restrict__ b,
            const float* __restrict__ lin,
            const float* __restrict__ uin,
            float* __restrict__ out) {
    float2* __restrict__ out2 = reinterpret_cast<float2*>(out);
    const unsigned long long pol = mk_evict_last_policy();

    const int i = blockIdx.x * TPB + threadIdx.x;   // exactly N2 threads
    // i = (((bb*Hp + hp)*Wp + wp)*C2 + c2)
    int c2 = i & (C2 - 1);
    int t  = i >> 7;            // C2 == 128
    int wp = t & (Wp - 1);
    t >>= 6;
    int hp = t & (Hp - 1);
    int bb = t >> 6;
    const int base = ((bb * Hh + 2 * hp) * Ww + 2 * wp) * C2 + c2;
    // Window order matches reference patches: (0,0),(0,1),(1,0),(1,1)
    const int o1 = C2, o2 = WC2, o3 = WC2 + C2;

    // Inputs: streaming evict-first loads (read exactly once; must not
    // displace the pinned dirty output lines).
    // Outputs: evict_last-policy stores (L2-resident across replays).

    // ---- Phase 1: x -> argmax + out_x ----
    const float2 X0 = __ldcs(x + base), X1 = __ldcs(x + base + o1),
                 X2 = __ldcs(x + base + o2), X3 = __ldcs(x + base + o3);
    int idx[2];
    float2 ox;
    #pragma unroll
    for (int ln = 0; ln < 2; ln++) {
        float v0 = getc(X0, ln), v1 = getc(X1, ln), v2 = getc(X2, ln), v3 = getc(X3, ln);
        int k = 0; float best = v0;                       // first-max (strict >)
        if (v1 > best) { best = v1; k = 1; }
        if (v2 > best) { best = v2; k = 2; }
        if (v3 > best) { best = v3; k = 3; }
        idx[ln] = k;
        setc(ox, ln, best);
    }
    st_hint(out2 + i, ox, pol);

    // ---- Phase 2: bias -> out_bias + partial noms (bis - bi_j) ----
    const float2 I0 = __ldcs(bias + base), I1 = __ldcs(bias + base + o1),
                 I2 = __ldcs(bias + base + o2), I3 = __ldcs(bias + base + o3);
    float nb[2][4];
    float2 obi;
    #pragma unroll
    for (int ln = 0; ln < 2; ln++) {
        float v0 = getc(I0, ln), v1 = getc(I1, ln), v2 = getc(I2, ln), v3 = getc(I3, ln);
        float s = sel4(v0, v1, v2, v3, idx[ln]);
        setc(obi, ln, s);
        nb[ln][0] = s - v0; nb[ln][1] = s - v1; nb[ln][2] = s - v2; nb[ln][3] = s - v3;
    }
    st_hint(out2 + N2 + i, obi, pol);

    // ---- Phase 3: a -> out_a + full noms (nb + (as - a_j)) ----
    const float2 A0 = __ldcs(a + base), A1 = __ldcs(a + base + o1),
                 A2 = __ldcs(a + base + o2), A3 = __ldcs(a + base + o3);
    float2 oa;
    #pragma unroll
    for (int ln = 0; ln < 2; ln++) {
        float v0 = getc(A0, ln), v1 = getc(A1, ln), v2 = getc(A2, ln), v3 = getc(A3, ln);
        float s = sel4(v0, v1, v2, v3, idx[ln]);
        setc(oa, ln, s);
        nb[ln][0] += s - v0; nb[ln][1] += s - v1; nb[ln][2] += s - v2; nb[ln][3] += s - v3;
    }
    st_hint(out2 + 2 * N2 + i, oa, pol);

    // ---- Phase 4: b -> out_b + interval candidates (branchless) ----
    float lloc = -CUDART_INF_F;
    float uloc =  CUDART_INF_F;
    const float2 B0 = __ldcs(b + base), B1 = __ldcs(b + base + o1),
                 B2 = __ldcs(b + base + o2), B3 = __ldcs(b + base + o3);
    float2 ob;
    #pragma unroll
    for (int ln = 0; ln < 2; ln++) {
        float v0 = getc(B0, ln), v1 = getc(B1, ln), v2 = getc(B2, ln), v3 = getc(B3, ln);
        float s = sel4(v0, v1, v2, v3, idx[ln]);
        setc(ob, ln, s);
        float d[4] = { v0 - s, v1 - s, v2 - s, v3 - s };
        #pragma unroll
        for (int j = 0; j < 4; j++) {
            // j==idx: 0/0 -> NaN, but both guards are false, so never used.
            float q = __fdividef(nb[ln][j], d[j]);
            uloc = (d[j] > 0.0f) ? fminf(uloc, q) : uloc;
            lloc = (d[j] < 0.0f) ? fmaxf(lloc, q) : lloc;
        }
    }
    st_hint(out2 + 3 * N2 + i, ob, pol);

    // ---- Block reduction: warp shuffle -> shared -> 3 relaxed atomics ----
    #pragma unroll
    for (int off = 16; off; off >>= 1) {
        lloc = fmaxf(lloc, __shfl_xor_sync(0xffffffffu, lloc, off));
        uloc = fminf(uloc, __shfl_xor_sync(0xffffffffu, uloc, off));
    }
    __shared__ float sl[8], su[8];
    const int warp = threadIdx.x >> 5;
    const int lane = threadIdx.x & 31;
    if (lane == 0) { sl[warp] = lloc; su[warp] = uloc; }
    __syncthreads();
    if (threadIdx.x == 0) {
        float lb = sl[0], ub = su[0];
        #pragma unroll
        for (int w = 1; w < TPB / 32; w++) {
            lb = fmaxf(lb, sl[w]);
            ub = fminf(ub, su[w]);
        }
        // Unconditional relaxed L2 RMWs (no-op-safe at the +-inf identities).
        atomicMaxF(&g_lbits, lb);
        atomicMinF(&g_ubits, ub);
        if (atomicAdd(&g_count, 1u) == (unsigned)(NBLK - 1)) {
            // Last arriver: read lattice via relaxed RMWs (L2-coherent, never
            // stale-L1), clamp with input l/u, write the two output scalars,
            // reset the lattice for the next graph replay.
            float lf = __uint_as_float(atomicAdd(&g_lbits, 0u));
            float uf = __uint_as_float(atomicAdd(&g_ubits, 0u));
            out[SCAL]     = fmaxf(lin[0], lf);
            out[SCAL + 1] = fminf(uin[0], uf);
            atomicExch(&g_lbits, 0xFF800000u);
            atomicExch(&g_ubits, 0x7F800000u);
            atomicExch(&g_count, 0u);   // kernel boundary orders for next replay
        }
    }
}

extern "C" void kernel_launch(void* const* d_in, const int* in_sizes, int n_in,
                              void* d_out, int out_size) {
    const float2* x  = (const float2*)d_in[0];
    const float2* bi = (const float2*)d_in[1];
    const float2* a  = (const float2*)d_in[2];
    const float2* b  = (const float2*)d_in[3];
    const float*  l  = (const float*)d_in[4];
    const float*  u  = (const float*)d_in[5];
    float* out = (float*)d_out;

    pool_kernel<<<NBLK, TPB>>>(x, bi, a, b, l, u, out);   // single kernel
}